// round 8
// baseline (speedup 1.0000x reference)
#include <cuda_runtime.h>
#include <cuda_bf16.h>
#include <cstdint>

// Problem constants
#define B_ 64
#define T_ 256
#define H_ 256
#define G4_ 1024      // 4*H
#define KRAW 600      // 2*E
#define KP 640        // padded K (20 chunks of 32)
#define L_ 15
#define M_ (B_*T_)    // 16384

// ------------------------- device scratch (no allocations) -------------------------
__device__ __align__(16) __nv_bfloat16 d_xb[(size_t)M_ * KP];    // [16384, 640] bf16
__device__ __align__(16) __nv_bfloat16 d_wb[(size_t)2048 * KP];  // [2048, 640] bf16
__device__ float d_g[(size_t)2 * M_ * G4_];               // [dir][t(or s)][b][1024]
__device__ float d_h[(size_t)M_ * 2 * H_];                // [b][t][512] = [h_f | h_b]
__device__ float d_emis[(size_t)M_ * L_];                 // [b][t][15]
__device__ float d_hbuf[2 * 8 * 2 * 2048];                // [dir][bbt][buf][unit*8+batch]
__device__ float d_partial[B_];
__device__ unsigned g_cnt[16];                            // per (dir,bbt) group counters

// ------------------------- helpers -------------------------
__device__ __forceinline__ float sigm(float x) {
    float e = __expf(-x);
    return __fdividef(1.0f, 1.0f + e);
}
__device__ __forceinline__ float tanh_ap(float x) {
    float y;
    asm("tanh.approx.f32 %0, %1;" : "=f"(y) : "f"(x));
    return y;
}
__device__ __forceinline__ float sel4(float4 v, int j) {
    float x = v.x;
    x = (j == 1) ? v.y : x;
    x = (j == 2) ? v.z : x;
    x = (j == 3) ? v.w : x;
    return x;
}
__device__ __forceinline__ uint32_t smem_u32(const void* p) {
    uint32_t a;
    asm("{ .reg .u64 t; cvta.to.shared.u64 t, %1; cvt.u32.u64 %0, t; }" : "=r"(a) : "l"(p));
    return a;
}
// packed f32x2 helpers
__device__ __forceinline__ unsigned long long pack2(float a, float b) {
    unsigned long long r;
    asm("mov.b64 %0, {%1, %2};" : "=l"(r) : "f"(a), "f"(b));
    return r;
}
__device__ __forceinline__ void ffma2(unsigned long long& d, unsigned long long a,
                                      unsigned long long b) {
    asm("fma.rn.f32x2 %0, %1, %2, %0;" : "+l"(d) : "l"(a), "l"(b));
}
__device__ __forceinline__ float2 unpack2(unsigned long long v) {
    float2 r;
    asm("mov.b64 {%0, %1}, %2;" : "=f"(r.x), "=f"(r.y) : "l"(v));
    return r;
}

// ------------------------- K0: reset barrier counters -------------------------
__global__ void k_init() {
    if (threadIdx.x < 16) g_cnt[threadIdx.x] = 0u;
}

// ------------------------- K1: embedding gather + concat + bf16 + pad -------------------------
__global__ void k_embed(const int* __restrict__ ids, const int* __restrict__ sids,
                        const float* __restrict__ emb, const float* __restrict__ semb) {
    int m = blockIdx.x;
    int c = threadIdx.x;
    __nv_bfloat16* xp = d_xb + (size_t)m * KP;
    if (c < 300) {
        int id = ids[m];
        int sid = sids[m];
        xp[c]       = __float2bfloat16_rn(emb[(size_t)id * 300 + c]);
        xp[300 + c] = __float2bfloat16_rn(semb[(size_t)sid * 300 + c]);
    } else {
        int z = c - 300;
        xp[600 + z] = __float2bfloat16_rn(0.f);
        xp[620 + z] = __float2bfloat16_rn(0.f);
    }
}

// ------------------------- K1b: weight conversion to bf16 (padded) -------------------------
__global__ void k_wconv(const float* __restrict__ Wf, const float* __restrict__ Wb) {
    int idx = blockIdx.x * blockDim.x + threadIdx.x;
    if (idx >= 2048 * KP) return;
    int row = idx / KP, k = idx - row * KP;
    float v = 0.f;
    if (k < KRAW) v = (row < 1024) ? Wf[row * KRAW + k] : Wb[(row - 1024) * KRAW + k];
    d_wb[idx] = __float2bfloat16_rn(v);
}

// ------------------------- K2: mma.sync bf16 GEMM (unchanged, proven) -------------------------
#define APITCH 40

__device__ __forceinline__ void ldm_x4(uint32_t* r, uint32_t addr) {
    asm volatile("ldmatrix.sync.aligned.m8n8.x4.shared.b16 {%0,%1,%2,%3}, [%4];"
                 : "=r"(r[0]), "=r"(r[1]), "=r"(r[2]), "=r"(r[3]) : "r"(addr));
}
__device__ __forceinline__ void mma16816(float* c, const uint32_t* a, const uint32_t* b) {
    asm volatile(
        "mma.sync.aligned.m16n8k16.row.col.f32.bf16.bf16.f32 "
        "{%0,%1,%2,%3}, {%4,%5,%6,%7}, {%8,%9}, {%0,%1,%2,%3};"
        : "+f"(c[0]), "+f"(c[1]), "+f"(c[2]), "+f"(c[3])
        : "r"(a[0]), "r"(a[1]), "r"(a[2]), "r"(a[3]), "r"(b[0]), "r"(b[1]));
}

__global__ void __launch_bounds__(256, 1)
k_gemm_mma(const float* __restrict__ bihf, const float* __restrict__ bhhf,
           const float* __restrict__ bihb, const float* __restrict__ bhhb,
           const int* __restrict__ lengths) {
    __shared__ __align__(16) __nv_bfloat16 sA[2][128][APITCH];
    __shared__ __align__(16) __nv_bfloat16 sB[2][128][APITCH];

    int tid = threadIdx.x;
    int wid = tid >> 5;
    int lane = tid & 31;
    int warpM = wid & 3;
    int warpN = wid >> 2;
    int m0 = blockIdx.y * 128;
    int n0g = blockIdx.x * 128;
    int dir = n0g >> 10;
    int n0 = n0g & 1023;

    const __nv_bfloat16* xa = d_xb + (size_t)m0 * KP;
    const __nv_bfloat16* wa = d_wb + (size_t)n0g * KP;

    int v0 = tid * 2;
    int r0i = v0 >> 2, j0 = v0 & 3;
    int v1 = v0 + 1;
    int r1i = v1 >> 2, j1 = v1 & 3;

    float acc[2][8][4];
#pragma unroll
    for (int mf = 0; mf < 2; mf++)
#pragma unroll
        for (int nf = 0; nf < 8; nf++)
#pragma unroll
            for (int q = 0; q < 4; q++) acc[mf][nf][q] = 0.f;

    {
        uint4 a0 = *(const uint4*)(xa + (size_t)r0i * KP + j0 * 8);
        uint4 a1 = *(const uint4*)(xa + (size_t)r1i * KP + j1 * 8);
        uint4 b0 = *(const uint4*)(wa + (size_t)r0i * KP + j0 * 8);
        uint4 b1 = *(const uint4*)(wa + (size_t)r1i * KP + j1 * 8);
        *(uint4*)&sA[0][r0i][j0 * 8] = a0;
        *(uint4*)&sA[0][r1i][j1 * 8] = a1;
        *(uint4*)&sB[0][r0i][j0 * 8] = b0;
        *(uint4*)&sB[0][r1i][j1 * 8] = b1;
    }
    __syncthreads();

    int aRow = warpM * 32 + (lane & 15);
    int aCol = (lane >> 4) << 3;
    int bRowBase = warpN * 64 + ((lane >> 4) << 3) + (lane & 7);
    int bCol = ((lane >> 3) & 1) << 3;

    for (int c = 0; c < 20; c++) {
        int buf = c & 1;
        uint4 na0, na1, nb0, nb1;
        if (c + 1 < 20) {
            const __nv_bfloat16* xan = xa + (c + 1) * 32;
            const __nv_bfloat16* wan = wa + (c + 1) * 32;
            na0 = *(const uint4*)(xan + (size_t)r0i * KP + j0 * 8);
            na1 = *(const uint4*)(xan + (size_t)r1i * KP + j1 * 8);
            nb0 = *(const uint4*)(wan + (size_t)r0i * KP + j0 * 8);
            nb1 = *(const uint4*)(wan + (size_t)r1i * KP + j1 * 8);
        }
#pragma unroll
        for (int ks = 0; ks < 2; ks++) {
            int kc = ks * 16;
            uint32_t af[2][4];
#pragma unroll
            for (int mf = 0; mf < 2; mf++)
                ldm_x4(af[mf], smem_u32(&sA[buf][aRow + mf * 16][kc + aCol]));
            uint32_t bf[4][4];
#pragma unroll
            for (int p = 0; p < 4; p++)
                ldm_x4(bf[p], smem_u32(&sB[buf][bRowBase + p * 16][kc + bCol]));
#pragma unroll
            for (int mf = 0; mf < 2; mf++)
#pragma unroll
                for (int nf = 0; nf < 8; nf++)
                    mma16816(acc[mf][nf], af[mf], &bf[nf >> 1][(nf & 1) * 2]);
        }
        if (c + 1 < 20) {
            int nb = (c + 1) & 1;
            *(uint4*)&sA[nb][r0i][j0 * 8] = na0;
            *(uint4*)&sA[nb][r1i][j1 * 8] = na1;
            *(uint4*)&sB[nb][r0i][j0 * 8] = nb0;
            *(uint4*)&sB[nb][r1i][j1 * 8] = nb1;
            __syncthreads();
        }
    }

    const float* bihp = dir ? bihb : bihf;
    const float* bhhp = dir ? bhhb : bhhf;
    int groupID = lane >> 2;
    int qn = (lane & 3) * 2;
#pragma unroll
    for (int mf = 0; mf < 2; mf++) {
#pragma unroll
        for (int mr = 0; mr < 2; mr++) {
            int m = m0 + warpM * 32 + mf * 16 + groupID + mr * 8;
            int b = m >> 8, t = m & 255;
            int row = t;
            if (dir) {
                int len = lengths[b];
                row = (t < len) ? (len - 1 - t) : t;
            }
            float* outp = d_g + ((size_t)dir * M_ + (size_t)row * B_ + b) * G4_;
#pragma unroll
            for (int nf = 0; nf < 8; nf++) {
                int n = n0 + warpN * 64 + nf * 8 + qn;
                float2 o;
                o.x = acc[mf][nf][mr * 2 + 0] + bihp[n] + bhhp[n];
                o.y = acc[mf][nf][mr * 2 + 1] + bihp[n + 1] + bhhp[n + 1];
                *(float2*)(outp + n) = o;
            }
        }
    }
}

// ------------------------- K3: persistent bidirectional LSTM recurrence -------------------------
// vs R7 (single-variable pair, both targeting the measured LSU+sync bound):
//  (a) phase-1 h loads via LDS.128 (ulonglong2) -> 64 LDS/thread instead of 128
//  (b) all-thread volatile spin on the group counter instead of tid0-spin + release
__global__ void __launch_bounds__(256, 1)
k_rec(const float* __restrict__ Whh_f, const float* __restrict__ Whh_b,
      const int* __restrict__ lengths) {
    __shared__ __align__(16) float sH[2048];   // [unit*8 + batch]
    __shared__ float4 sRed[8 * 8 * 32];        // [kc][bb][rowgroup] partial gate sums

    int tid = threadIdx.x;
    int bx = blockIdx.x;
    int dir = bx >> 6;
    int r6 = bx & 63;
    int bbt = r6 >> 3;
    int ut = r6 & 7;
    int u0 = ut * 32;
    int grp = dir * 8 + bbt;
    const float* Whh = dir ? Whh_b : Whh_f;
    const float* gbase = d_g + (size_t)dir * M_ * G4_;
    float* hbufGrp = d_hbuf + (size_t)grp * 2 * 2048;

    int kc = tid >> 5;   // 0..7 (uniform per warp)
    int rg = tid & 31;   // 0..31

    int bb2 = tid >> 5;  // 0..7
    int q2 = tid & 31;   // 0..31
    int batch2 = bbt * 8 + bb2;
    int len2 = lengths[batch2];
    int jsel = q2 & 3;

    // Whh slice in registers (same mapping as R5/R7)
    float W[4][32];
#pragma unroll
    for (int j = 0; j < 4; j++) {
        int r = rg * 4 + j;
        int grow = (r >> 5) * 256 + u0 + (r & 31);
        const float* wp = Whh + (size_t)grow * 256 + kc * 32;
#pragma unroll
        for (int kk = 0; kk < 32; kk += 4) {
            float4 v = *(const float4*)(wp + kk);
            W[j][kk] = v.x; W[j][kk + 1] = v.y; W[j][kk + 2] = v.z; W[j][kk + 3] = v.w;
        }
    }

    for (int i = tid; i < 2048; i += 256) sH[i] = 0.f;

    float c = 0.f;
    unsigned target = 0;
    __syncthreads();

    for (int step = 0; step < 256; step++) {
        // prefetch this step's x-part gates (hide latency behind phase 1)
        const float* gx = gbase + ((size_t)step * B_ + batch2) * G4_;
        float gpre[4];
#pragma unroll
        for (int g = 0; g < 4; g++) gpre[g] = gx[g * 256 + u0 + q2];

        // ---- phase 1: packed f32x2 partials, h octets loaded via LDS.128 ----
        unsigned long long acc2[4][4];   // [bbpair][j]
#pragma unroll
        for (int p = 0; p < 4; p++)
#pragma unroll
            for (int j = 0; j < 4; j++) acc2[p][j] = pack2(0.f, 0.f);

        const ulonglong2* hp2 = (const ulonglong2*)&sH[kc * 256];  // [kk][2 x u64-pair]
#pragma unroll
        for (int kk = 0; kk < 32; kk++) {
            ulonglong2 ha = hp2[kk * 2 + 0];   // batches 0..3
            ulonglong2 hb = hp2[kk * 2 + 1];   // batches 4..7
            unsigned long long h0 = ha.x, h1 = ha.y, h2 = hb.x, h3 = hb.y;
#pragma unroll
            for (int j = 0; j < 4; j++) {
                unsigned long long w2 = pack2(W[j][kk], W[j][kk]);
                ffma2(acc2[0][j], h0, w2);
                ffma2(acc2[1][j], h1, w2);
                ffma2(acc2[2][j], h2, w2);
                ffma2(acc2[3][j], h3, w2);
            }
        }
#pragma unroll
        for (int p = 0; p < 4; p++) {
            float4 lo, hi;
            float2 u0v = unpack2(acc2[p][0]);
            float2 u1v = unpack2(acc2[p][1]);
            float2 u2v = unpack2(acc2[p][2]);
            float2 u3v = unpack2(acc2[p][3]);
            lo.x = u0v.x; lo.y = u1v.x; lo.z = u2v.x; lo.w = u3v.x;
            hi.x = u0v.y; hi.y = u1v.y; hi.z = u2v.y; hi.w = u3v.y;
            sRed[(kc * 8 + p * 2 + 0) * 32 + rg] = lo;
            sRed[(kc * 8 + p * 2 + 1) * 32 + rg] = hi;
        }
        __syncthreads();

        // ---- phase 2: gates, cell update, h out ----
        float gate[4];
#pragma unroll
        for (int g = 0; g < 4; g++) {
            int rgl = g * 8 + (q2 >> 2);
            float s = gpre[g];
#pragma unroll
            for (int kcc = 0; kcc < 8; kcc++)
                s += sel4(sRed[(kcc * 8 + bb2) * 32 + rgl], jsel);
            gate[g] = s;
        }
        float i_ = sigm(gate[0]);
        float f_ = sigm(gate[1]);
        float gg = tanh_ap(gate[2]);
        float o_ = sigm(gate[3]);
        c = f_ * c + i_ * gg;
        float h = o_ * tanh_ap(c);

        int wbuf = step & 1;
        __stcg(&hbufGrp[wbuf * 2048 + (u0 + q2) * 8 + bb2], h);
        int tout = dir ? ((step < len2) ? (len2 - 1 - step) : step) : step;
        d_h[((size_t)batch2 * T_ + tout) * 512 + dir * 256 + u0 + q2] = h;

        // ---- group barrier: one arrival, all threads spin ----
        __threadfence();
        __syncthreads();
        target += 8;
        if (tid == 0) atomicAdd(&g_cnt[grp], 1u);
        {
            volatile unsigned* cp = &g_cnt[grp];
            while (*cp < target) { }
        }
        __threadfence();

        // ---- reload full h_prev (contiguous, unit-major) ----
        const float4* src = (const float4*)(hbufGrp + wbuf * 2048);
        ((float4*)sH)[tid]       = __ldcg(src + tid);
        ((float4*)sH)[tid + 256] = __ldcg(src + tid + 256);
        __syncthreads();
    }
}

// ------------------------- K4: emissions = h . Wlin^T + blin -------------------------
__global__ void __launch_bounds__(128)
k_emis(const float* __restrict__ Wlin, const float* __restrict__ blin) {
    __shared__ float sW[15 * 516];
    __shared__ float sh[8 * 512];
    int tid = threadIdx.x;
    for (int i = tid; i < 15 * 512; i += 128) {
        int l = i >> 9, k = i & 511;
        sW[l * 516 + k] = Wlin[i];
    }
    int m0 = blockIdx.x * 8;
    const float4* hsrc = (const float4*)(d_h + (size_t)m0 * 512);
    for (int i = tid; i < 8 * 512 / 4; i += 128)
        ((float4*)sh)[i] = hsrc[i];
    __syncthreads();

    int r = tid >> 4, l = tid & 15;
    if (l < 15) {
        float s = blin[l];
        const float* hw = sh + r * 512;
        const float* ww = sW + l * 516;
#pragma unroll 8
        for (int k = 0; k < 512; k += 4) {
            float4 hv = *(const float4*)(hw + k);
            float4 wv = *(const float4*)(ww + k);
            s += hv.x * wv.x + hv.y * wv.y + hv.z * wv.z + hv.w * wv.w;
        }
        d_emis[(size_t)(m0 + r) * L_ + l] = s;
    }
}

// ------------------------- K5: CRF NLL per sequence -------------------------
__global__ void k_crf(const int* __restrict__ lengths, const int* __restrict__ labels,
                      const float* __restrict__ start_t, const float* __restrict__ end_t,
                      const float* __restrict__ trans) {
    int b = blockIdx.x;
    int lane = threadIdx.x;
    int len = lengths[b];
    const float* em = d_emis + (size_t)b * T_ * L_;
    int j = (lane < L_) ? lane : 0;

    float tr[L_];
#pragma unroll
    for (int i = 0; i < L_; i++) tr[i] = trans[i * L_ + j];

    float alpha = start_t[j] + em[j];
    for (int t = 1; t < T_; t++) {
        float v[L_], mx = -1e30f;
#pragma unroll
        for (int i = 0; i < L_; i++) {
            float av = __shfl_sync(0xffffffffu, alpha, i);
            v[i] = av + tr[i];
            mx = fmaxf(mx, v[i]);
        }
        float s = 0.f;
#pragma unroll
        for (int i = 0; i < L_; i++) s += __expf(v[i] - mx);
        float nxt = mx + __logf(s) + em[t * L_ + j];
        if (t < len) alpha = nxt;
    }
    float vv = (lane < L_) ? (alpha + end_t[lane]) : -1e30f;
    float mx = vv;
#pragma unroll
    for (int o = 16; o; o >>= 1) mx = fmaxf(mx, __shfl_xor_sync(0xffffffffu, mx, o));
    float se = (lane < L_) ? __expf(vv - mx) : 0.f;
#pragma unroll
    for (int o = 16; o; o >>= 1) se += __shfl_xor_sync(0xffffffffu, se, o);
    float den = mx + __logf(se);

    const int* tg = labels + b * T_;
    float em_s = 0.f, tr_s = 0.f;
    for (int t = lane; t < T_; t += 32) {
        if (t < len) {
            em_s += em[t * L_ + tg[t]];
            if (t >= 1) tr_s += trans[tg[t - 1] * L_ + tg[t]];
        }
    }
#pragma unroll
    for (int o = 16; o; o >>= 1) {
        em_s += __shfl_xor_sync(0xffffffffu, em_s, o);
        tr_s += __shfl_xor_sync(0xffffffffu, tr_s, o);
    }
    if (lane == 0) {
        float num = start_t[tg[0]] + em_s + tr_s + end_t[tg[len - 1]];
        d_partial[b] = num - den;
    }
}

// ------------------------- K6: deterministic final sum -------------------------
__global__ void k_final(float* __restrict__ out) {
    float s = 0.f;
#pragma unroll
    for (int b = 0; b < B_; b++) s += d_partial[b];
    out[0] = -s;
}

// ------------------------- launch -------------------------
extern "C" void kernel_launch(void* const* d_in, const int* in_sizes, int n_in,
                              void* d_out, int out_size) {
    const int*   input_ids    = (const int*)d_in[0];
    const int*   lengths      = (const int*)d_in[1];
    const int*   softword_ids = (const int*)d_in[2];
    const int*   label_ids    = (const int*)d_in[3];
    const float* emb          = (const float*)d_in[4];
    const float* soft_emb     = (const float*)d_in[5];
    const float* Wih_f        = (const float*)d_in[6];
    const float* Whh_f        = (const float*)d_in[7];
    const float* bih_f        = (const float*)d_in[8];
    const float* bhh_f        = (const float*)d_in[9];
    const float* Wih_b        = (const float*)d_in[10];
    const float* Whh_b        = (const float*)d_in[11];
    const float* bih_b        = (const float*)d_in[12];
    const float* bhh_b        = (const float*)d_in[13];
    const float* Wlin         = (const float*)d_in[14];
    const float* blin         = (const float*)d_in[15];
    const float* start_t      = (const float*)d_in[16];
    const float* end_t        = (const float*)d_in[17];
    const float* trans        = (const float*)d_in[18];
    float* out = (float*)d_out;

    k_init<<<1, 32>>>();
    k_embed<<<M_, 320>>>(input_ids, softword_ids, emb, soft_emb);
    k_wconv<<<(2048 * KP + 511) / 512, 512>>>(Wih_f, Wih_b);
    dim3 g2(16, 128);
    k_gemm_mma<<<g2, 256>>>(bih_f, bhh_f, bih_b, bhh_b, lengths);
    k_rec<<<128, 256>>>(Whh_f, Whh_b, lengths);
    k_emis<<<2048, 128>>>(Wlin, blin);
    k_crf<<<B_, 32>>>(lengths, label_ids, start_t, end_t, trans);
    k_final<<<1, 1>>>(out);
}

// round 9
// speedup vs baseline: 1.5634x; 1.5634x over previous
#include <cuda_runtime.h>
#include <cuda_bf16.h>
#include <cstdint>

// Problem constants
#define B_ 64
#define T_ 256
#define H_ 256
#define G4_ 1024      // 4*H
#define KRAW 600      // 2*E
#define KP 640        // padded K (20 chunks of 32)
#define L_ 15
#define M_ (B_*T_)    // 16384

// ------------------------- device scratch (no allocations) -------------------------
__device__ __align__(16) __nv_bfloat16 d_xb[(size_t)M_ * KP];    // [16384, 640] bf16
__device__ __align__(16) __nv_bfloat16 d_wb[(size_t)2048 * KP];  // [2048, 640] bf16
__device__ float d_g[(size_t)2 * M_ * G4_];               // [dir][t(or s)][b][1024]
__device__ float d_h[(size_t)M_ * 2 * H_];                // [b][t][512] = [h_f | h_b]
__device__ float d_emis[(size_t)M_ * L_];                 // [b][t][15]
__device__ float d_hbuf[2 * 8 * 2 * 2048];                // [dir][bbt][buf][unit*8+batch]
__device__ float d_partial[B_];
__device__ unsigned g_cnt[16];                            // per (dir,bbt) group counters

// ------------------------- helpers -------------------------
__device__ __forceinline__ float sigm(float x) {
    float e = __expf(-x);
    return __fdividef(1.0f, 1.0f + e);
}
__device__ __forceinline__ float tanh_ap(float x) {
    float y;
    asm("tanh.approx.f32 %0, %1;" : "=f"(y) : "f"(x));
    return y;
}
__device__ __forceinline__ float sel4(float4 v, int j) {
    float x = v.x;
    x = (j == 1) ? v.y : x;
    x = (j == 2) ? v.z : x;
    x = (j == 3) ? v.w : x;
    return x;
}
__device__ __forceinline__ uint32_t smem_u32(const void* p) {
    uint32_t a;
    asm("{ .reg .u64 t; cvta.to.shared.u64 t, %1; cvt.u32.u64 %0, t; }" : "=r"(a) : "l"(p));
    return a;
}
// packed f32x2 helpers
__device__ __forceinline__ unsigned long long pack2(float a, float b) {
    unsigned long long r;
    asm("mov.b64 %0, {%1, %2};" : "=l"(r) : "f"(a), "f"(b));
    return r;
}
__device__ __forceinline__ void ffma2(unsigned long long& d, unsigned long long a,
                                      unsigned long long b) {
    asm("fma.rn.f32x2 %0, %1, %2, %0;" : "+l"(d) : "l"(a), "l"(b));
}
__device__ __forceinline__ float2 unpack2(unsigned long long v) {
    float2 r;
    asm("mov.b64 {%0, %1}, %2;" : "=f"(r.x), "=f"(r.y) : "l"(v));
    return r;
}

// ------------------------- K0: reset barrier counters -------------------------
__global__ void k_init() {
    if (threadIdx.x < 16) g_cnt[threadIdx.x] = 0u;
}

// ------------------------- K1: embedding gather + concat + bf16 + pad -------------------------
__global__ void k_embed(const int* __restrict__ ids, const int* __restrict__ sids,
                        const float* __restrict__ emb, const float* __restrict__ semb) {
    int m = blockIdx.x;
    int c = threadIdx.x;
    __nv_bfloat16* xp = d_xb + (size_t)m * KP;
    if (c < 300) {
        int id = ids[m];
        int sid = sids[m];
        xp[c]       = __float2bfloat16_rn(emb[(size_t)id * 300 + c]);
        xp[300 + c] = __float2bfloat16_rn(semb[(size_t)sid * 300 + c]);
    } else {
        int z = c - 300;
        xp[600 + z] = __float2bfloat16_rn(0.f);
        xp[620 + z] = __float2bfloat16_rn(0.f);
    }
}

// ------------------------- K1b: weight conversion to bf16 (padded) -------------------------
__global__ void k_wconv(const float* __restrict__ Wf, const float* __restrict__ Wb) {
    int idx = blockIdx.x * blockDim.x + threadIdx.x;
    if (idx >= 2048 * KP) return;
    int row = idx / KP, k = idx - row * KP;
    float v = 0.f;
    if (k < KRAW) v = (row < 1024) ? Wf[row * KRAW + k] : Wb[(row - 1024) * KRAW + k];
    d_wb[idx] = __float2bfloat16_rn(v);
}

// ------------------------- K2: mma.sync bf16 GEMM (R7 + 2 CTAs/SM) -------------------------
#define APITCH 40

__device__ __forceinline__ void ldm_x4(uint32_t* r, uint32_t addr) {
    asm volatile("ldmatrix.sync.aligned.m8n8.x4.shared.b16 {%0,%1,%2,%3}, [%4];"
                 : "=r"(r[0]), "=r"(r[1]), "=r"(r[2]), "=r"(r[3]) : "r"(addr));
}
__device__ __forceinline__ void mma16816(float* c, const uint32_t* a, const uint32_t* b) {
    asm volatile(
        "mma.sync.aligned.m16n8k16.row.col.f32.bf16.bf16.f32 "
        "{%0,%1,%2,%3}, {%4,%5,%6,%7}, {%8,%9}, {%0,%1,%2,%3};"
        : "+f"(c[0]), "+f"(c[1]), "+f"(c[2]), "+f"(c[3])
        : "r"(a[0]), "r"(a[1]), "r"(a[2]), "r"(a[3]), "r"(b[0]), "r"(b[1]));
}

__global__ void __launch_bounds__(256, 2)
k_gemm_mma(const float* __restrict__ bihf, const float* __restrict__ bhhf,
           const float* __restrict__ bihb, const float* __restrict__ bhhb,
           const int* __restrict__ lengths) {
    __shared__ __align__(16) __nv_bfloat16 sA[2][128][APITCH];
    __shared__ __align__(16) __nv_bfloat16 sB[2][128][APITCH];

    int tid = threadIdx.x;
    int wid = tid >> 5;
    int lane = tid & 31;
    int warpM = wid & 3;
    int warpN = wid >> 2;
    int m0 = blockIdx.y * 128;
    int n0g = blockIdx.x * 128;
    int dir = n0g >> 10;
    int n0 = n0g & 1023;

    const __nv_bfloat16* xa = d_xb + (size_t)m0 * KP;
    const __nv_bfloat16* wa = d_wb + (size_t)n0g * KP;

    int v0 = tid * 2;
    int r0i = v0 >> 2, j0 = v0 & 3;
    int v1 = v0 + 1;
    int r1i = v1 >> 2, j1 = v1 & 3;

    float acc[2][8][4];
#pragma unroll
    for (int mf = 0; mf < 2; mf++)
#pragma unroll
        for (int nf = 0; nf < 8; nf++)
#pragma unroll
            for (int q = 0; q < 4; q++) acc[mf][nf][q] = 0.f;

    {
        uint4 a0 = *(const uint4*)(xa + (size_t)r0i * KP + j0 * 8);
        uint4 a1 = *(const uint4*)(xa + (size_t)r1i * KP + j1 * 8);
        uint4 b0 = *(const uint4*)(wa + (size_t)r0i * KP + j0 * 8);
        uint4 b1 = *(const uint4*)(wa + (size_t)r1i * KP + j1 * 8);
        *(uint4*)&sA[0][r0i][j0 * 8] = a0;
        *(uint4*)&sA[0][r1i][j1 * 8] = a1;
        *(uint4*)&sB[0][r0i][j0 * 8] = b0;
        *(uint4*)&sB[0][r1i][j1 * 8] = b1;
    }
    __syncthreads();

    int aRow = warpM * 32 + (lane & 15);
    int aCol = (lane >> 4) << 3;
    int bRowBase = warpN * 64 + ((lane >> 4) << 3) + (lane & 7);
    int bCol = ((lane >> 3) & 1) << 3;

    for (int c = 0; c < 20; c++) {
        int buf = c & 1;
        uint4 na0, na1, nb0, nb1;
        if (c + 1 < 20) {
            const __nv_bfloat16* xan = xa + (c + 1) * 32;
            const __nv_bfloat16* wan = wa + (c + 1) * 32;
            na0 = *(const uint4*)(xan + (size_t)r0i * KP + j0 * 8);
            na1 = *(const uint4*)(xan + (size_t)r1i * KP + j1 * 8);
            nb0 = *(const uint4*)(wan + (size_t)r0i * KP + j0 * 8);
            nb1 = *(const uint4*)(wan + (size_t)r1i * KP + j1 * 8);
        }
#pragma unroll
        for (int ks = 0; ks < 2; ks++) {
            int kc = ks * 16;
            uint32_t af[2][4];
#pragma unroll
            for (int mf = 0; mf < 2; mf++)
                ldm_x4(af[mf], smem_u32(&sA[buf][aRow + mf * 16][kc + aCol]));
            uint32_t bf[4][4];
#pragma unroll
            for (int p = 0; p < 4; p++)
                ldm_x4(bf[p], smem_u32(&sB[buf][bRowBase + p * 16][kc + bCol]));
#pragma unroll
            for (int mf = 0; mf < 2; mf++)
#pragma unroll
                for (int nf = 0; nf < 8; nf++)
                    mma16816(acc[mf][nf], af[mf], &bf[nf >> 1][(nf & 1) * 2]);
        }
        if (c + 1 < 20) {
            int nb = (c + 1) & 1;
            *(uint4*)&sA[nb][r0i][j0 * 8] = na0;
            *(uint4*)&sA[nb][r1i][j1 * 8] = na1;
            *(uint4*)&sB[nb][r0i][j0 * 8] = nb0;
            *(uint4*)&sB[nb][r1i][j1 * 8] = nb1;
            __syncthreads();
        }
    }

    const float* bihp = dir ? bihb : bihf;
    const float* bhhp = dir ? bhhb : bhhf;
    int groupID = lane >> 2;
    int qn = (lane & 3) * 2;
#pragma unroll
    for (int mf = 0; mf < 2; mf++) {
#pragma unroll
        for (int mr = 0; mr < 2; mr++) {
            int m = m0 + warpM * 32 + mf * 16 + groupID + mr * 8;
            int b = m >> 8, t = m & 255;
            int row = t;
            if (dir) {
                int len = lengths[b];
                row = (t < len) ? (len - 1 - t) : t;
            }
            float* outp = d_g + ((size_t)dir * M_ + (size_t)row * B_ + b) * G4_;
#pragma unroll
            for (int nf = 0; nf < 8; nf++) {
                int n = n0 + warpN * 64 + nf * 8 + qn;
                float2 o;
                o.x = acc[mf][nf][mr * 2 + 0] + bihp[n] + bhhp[n];
                o.y = acc[mf][nf][mr * 2 + 1] + bihp[n + 1] + bhhp[n + 1];
                *(float2*)(outp + n) = o;
            }
        }
    }
}

// ------------------------- K3: persistent bidirectional LSTM recurrence -------------------------
// R7-proven barrier (tid0 spin + syncthreads release). Changes vs R7:
//  (a) phase-1 h loads via LDS.128 (ulonglong2)
//  (b) d_g gate loads prefetched ONE FULL STEP ahead (register double-buffer)
__global__ void __launch_bounds__(256, 1)
k_rec(const float* __restrict__ Whh_f, const float* __restrict__ Whh_b,
      const int* __restrict__ lengths) {
    __shared__ __align__(16) float sH[2048];   // [unit*8 + batch]
    __shared__ float4 sRed[8 * 8 * 32];        // [kc][bb][rowgroup] partial gate sums

    int tid = threadIdx.x;
    int bx = blockIdx.x;
    int dir = bx >> 6;
    int r6 = bx & 63;
    int bbt = r6 >> 3;
    int ut = r6 & 7;
    int u0 = ut * 32;
    int grp = dir * 8 + bbt;
    const float* Whh = dir ? Whh_b : Whh_f;
    const float* gbase = d_g + (size_t)dir * M_ * G4_;
    float* hbufGrp = d_hbuf + (size_t)grp * 2 * 2048;

    int kc = tid >> 5;   // 0..7 (uniform per warp)
    int rg = tid & 31;   // 0..31

    int bb2 = tid >> 5;  // 0..7
    int q2 = tid & 31;   // 0..31
    int batch2 = bbt * 8 + bb2;
    int len2 = lengths[batch2];
    int jsel = q2 & 3;

    // Whh slice in registers (same mapping as R5/R7)
    float W[4][32];
#pragma unroll
    for (int j = 0; j < 4; j++) {
        int r = rg * 4 + j;
        int grow = (r >> 5) * 256 + u0 + (r & 31);
        const float* wp = Whh + (size_t)grow * 256 + kc * 32;
#pragma unroll
        for (int kk = 0; kk < 32; kk += 4) {
            float4 v = *(const float4*)(wp + kk);
            W[j][kk] = v.x; W[j][kk + 1] = v.y; W[j][kk + 2] = v.z; W[j][kk + 3] = v.w;
        }
    }

    for (int i = tid; i < 2048; i += 256) sH[i] = 0.f;

    float c = 0.f;
    unsigned target = 0;
    __syncthreads();

    // preload step 0's gates
    float gpre[4];
    {
        const float* gx = gbase + (size_t)batch2 * G4_;
#pragma unroll
        for (int g = 0; g < 4; g++) gpre[g] = gx[g * 256 + u0 + q2];
    }

    for (int step = 0; step < 256; step++) {
        // issue NEXT step's gate loads now (consumed next iteration -> full-step latency cover)
        float gnxt[4];
        if (step + 1 < 256) {
            const float* gx = gbase + ((size_t)(step + 1) * B_ + batch2) * G4_;
#pragma unroll
            for (int g = 0; g < 4; g++) gnxt[g] = __ldcg(&gx[g * 256 + u0 + q2]);
        }

        // ---- phase 1: packed f32x2 partials, h octets loaded via LDS.128 ----
        unsigned long long acc2[4][4];   // [bbpair][j]
#pragma unroll
        for (int p = 0; p < 4; p++)
#pragma unroll
            for (int j = 0; j < 4; j++) acc2[p][j] = pack2(0.f, 0.f);

        const ulonglong2* hp2 = (const ulonglong2*)&sH[kc * 256];
#pragma unroll
        for (int kk = 0; kk < 32; kk++) {
            ulonglong2 ha = hp2[kk * 2 + 0];   // batches 0..3
            ulonglong2 hb = hp2[kk * 2 + 1];   // batches 4..7
            unsigned long long h0 = ha.x, h1 = ha.y, h2 = hb.x, h3 = hb.y;
#pragma unroll
            for (int j = 0; j < 4; j++) {
                unsigned long long w2 = pack2(W[j][kk], W[j][kk]);
                ffma2(acc2[0][j], h0, w2);
                ffma2(acc2[1][j], h1, w2);
                ffma2(acc2[2][j], h2, w2);
                ffma2(acc2[3][j], h3, w2);
            }
        }
#pragma unroll
        for (int p = 0; p < 4; p++) {
            float4 lo, hi;
            float2 u0v = unpack2(acc2[p][0]);
            float2 u1v = unpack2(acc2[p][1]);
            float2 u2v = unpack2(acc2[p][2]);
            float2 u3v = unpack2(acc2[p][3]);
            lo.x = u0v.x; lo.y = u1v.x; lo.z = u2v.x; lo.w = u3v.x;
            hi.x = u0v.y; hi.y = u1v.y; hi.z = u2v.y; hi.w = u3v.y;
            sRed[(kc * 8 + p * 2 + 0) * 32 + rg] = lo;
            sRed[(kc * 8 + p * 2 + 1) * 32 + rg] = hi;
        }
        __syncthreads();

        // ---- phase 2: gates, cell update, h out ----
        float gate[4];
#pragma unroll
        for (int g = 0; g < 4; g++) {
            int rgl = g * 8 + (q2 >> 2);
            float s = gpre[g];
#pragma unroll
            for (int kcc = 0; kcc < 8; kcc++)
                s += sel4(sRed[(kcc * 8 + bb2) * 32 + rgl], jsel);
            gate[g] = s;
        }
        float i_ = sigm(gate[0]);
        float f_ = sigm(gate[1]);
        float gg = tanh_ap(gate[2]);
        float o_ = sigm(gate[3]);
        c = f_ * c + i_ * gg;
        float h = o_ * tanh_ap(c);

        int wbuf = step & 1;
        __stcg(&hbufGrp[wbuf * 2048 + (u0 + q2) * 8 + bb2], h);
        int tout = dir ? ((step < len2) ? (len2 - 1 - step) : step) : step;
        d_h[((size_t)batch2 * T_ + tout) * 512 + dir * 256 + u0 + q2] = h;

        // ---- group barrier (R7-proven: tid0 spin, syncthreads release) ----
        __threadfence();
        __syncthreads();
        target += 8;
        if (tid == 0) {
            atomicAdd(&g_cnt[grp], 1u);
            while (*(volatile unsigned*)&g_cnt[grp] < target) { }
            __threadfence();
        }
        __syncthreads();

        // ---- reload full h_prev (contiguous, unit-major) ----
        const float4* src = (const float4*)(hbufGrp + wbuf * 2048);
        ((float4*)sH)[tid]       = __ldcg(src + tid);
        ((float4*)sH)[tid + 256] = __ldcg(src + tid + 256);
        __syncthreads();

#pragma unroll
        for (int g = 0; g < 4; g++) gpre[g] = gnxt[g];
    }
}

// ------------------------- K4: emissions = h . Wlin^T + blin -------------------------
__global__ void __launch_bounds__(128)
k_emis(const float* __restrict__ Wlin, const float* __restrict__ blin) {
    __shared__ float sW[15 * 516];
    __shared__ float sh[8 * 512];
    int tid = threadIdx.x;
    for (int i = tid; i < 15 * 512; i += 128) {
        int l = i >> 9, k = i & 511;
        sW[l * 516 + k] = Wlin[i];
    }
    int m0 = blockIdx.x * 8;
    const float4* hsrc = (const float4*)(d_h + (size_t)m0 * 512);
    for (int i = tid; i < 8 * 512 / 4; i += 128)
        ((float4*)sh)[i] = hsrc[i];
    __syncthreads();

    int r = tid >> 4, l = tid & 15;
    if (l < 15) {
        float s = blin[l];
        const float* hw = sh + r * 512;
        const float* ww = sW + l * 516;
#pragma unroll 8
        for (int k = 0; k < 512; k += 4) {
            float4 hv = *(const float4*)(hw + k);
            float4 wv = *(const float4*)(ww + k);
            s += hv.x * wv.x + hv.y * wv.y + hv.z * wv.z + hv.w * wv.w;
        }
        d_emis[(size_t)(m0 + r) * L_ + l] = s;
    }
}

// ------------------------- K5: CRF NLL per sequence -------------------------
__global__ void k_crf(const int* __restrict__ lengths, const int* __restrict__ labels,
                      const float* __restrict__ start_t, const float* __restrict__ end_t,
                      const float* __restrict__ trans) {
    int b = blockIdx.x;
    int lane = threadIdx.x;
    int len = lengths[b];
    const float* em = d_emis + (size_t)b * T_ * L_;
    int j = (lane < L_) ? lane : 0;

    float tr[L_];
#pragma unroll
    for (int i = 0; i < L_; i++) tr[i] = trans[i * L_ + j];

    float alpha = start_t[j] + em[j];
    for (int t = 1; t < T_; t++) {
        float v[L_], mx = -1e30f;
#pragma unroll
        for (int i = 0; i < L_; i++) {
            float av = __shfl_sync(0xffffffffu, alpha, i);
            v[i] = av + tr[i];
            mx = fmaxf(mx, v[i]);
        }
        float s = 0.f;
#pragma unroll
        for (int i = 0; i < L_; i++) s += __expf(v[i] - mx);
        float nxt = mx + __logf(s) + em[t * L_ + j];
        if (t < len) alpha = nxt;
    }
    float vv = (lane < L_) ? (alpha + end_t[lane]) : -1e30f;
    float mx = vv;
#pragma unroll
    for (int o = 16; o; o >>= 1) mx = fmaxf(mx, __shfl_xor_sync(0xffffffffu, mx, o));
    float se = (lane < L_) ? __expf(vv - mx) : 0.f;
#pragma unroll
    for (int o = 16; o; o >>= 1) se += __shfl_xor_sync(0xffffffffu, se, o);
    float den = mx + __logf(se);

    const int* tg = labels + b * T_;
    float em_s = 0.f, tr_s = 0.f;
    for (int t = lane; t < T_; t += 32) {
        if (t < len) {
            em_s += em[t * L_ + tg[t]];
            if (t >= 1) tr_s += trans[tg[t - 1] * L_ + tg[t]];
        }
    }
#pragma unroll
    for (int o = 16; o; o >>= 1) {
        em_s += __shfl_xor_sync(0xffffffffu, em_s, o);
        tr_s += __shfl_xor_sync(0xffffffffu, tr_s, o);
    }
    if (lane == 0) {
        float num = start_t[tg[0]] + em_s + tr_s + end_t[tg[len - 1]];
        d_partial[b] = num - den;
    }
}

// ------------------------- K6: deterministic final sum -------------------------
__global__ void k_final(float* __restrict__ out) {
    float s = 0.f;
#pragma unroll
    for (int b = 0; b < B_; b++) s += d_partial[b];
    out[0] = -s;
}

// ------------------------- launch -------------------------
extern "C" void kernel_launch(void* const* d_in, const int* in_sizes, int n_in,
                              void* d_out, int out_size) {
    const int*   input_ids    = (const int*)d_in[0];
    const int*   lengths      = (const int*)d_in[1];
    const int*   softword_ids = (const int*)d_in[2];
    const int*   label_ids    = (const int*)d_in[3];
    const float* emb          = (const float*)d_in[4];
    const float* soft_emb     = (const float*)d_in[5];
    const float* Wih_f        = (const float*)d_in[6];
    const float* Whh_f        = (const float*)d_in[7];
    const float* bih_f        = (const float*)d_in[8];
    const float* bhh_f        = (const float*)d_in[9];
    const float* Wih_b        = (const float*)d_in[10];
    const float* Whh_b        = (const float*)d_in[11];
    const float* bih_b        = (const float*)d_in[12];
    const float* bhh_b        = (const float*)d_in[13];
    const float* Wlin         = (const float*)d_in[14];
    const float* blin         = (const float*)d_in[15];
    const float* start_t      = (const float*)d_in[16];
    const float* end_t        = (const float*)d_in[17];
    const float* trans        = (const float*)d_in[18];
    float* out = (float*)d_out;

    k_init<<<1, 32>>>();
    k_embed<<<M_, 320>>>(input_ids, softword_ids, emb, soft_emb);
    k_wconv<<<(2048 * KP + 511) / 512, 512>>>(Wih_f, Wih_b);
    dim3 g2(16, 128);
    k_gemm_mma<<<g2, 256>>>(bih_f, bhh_f, bih_b, bhh_b, lengths);
    k_rec<<<128, 256>>>(Whh_f, Whh_b, lengths);
    k_emis<<<2048, 128>>>(Wlin, blin);
    k_crf<<<B_, 32>>>(lengths, label_ids, start_t, end_t, trans);
    k_final<<<1, 1>>>(out);
}

// round 10
// speedup vs baseline: 1.8174x; 1.1625x over previous
#include <cuda_runtime.h>
#include <cuda_bf16.h>
#include <cstdint>

// Problem constants
#define B_ 64
#define T_ 256
#define H_ 256
#define G4_ 1024      // 4*H
#define KRAW 600      // 2*E
#define KP 640        // padded K (20 chunks of 32)
#define L_ 15
#define M_ (B_*T_)    // 16384

// ------------------------- device scratch (no allocations) -------------------------
__device__ __align__(16) __nv_bfloat16 d_xb[(size_t)M_ * KP];    // [16384, 640] bf16
__device__ __align__(16) __nv_bfloat16 d_wb[(size_t)2048 * KP];  // [2048, 640] bf16
__device__ float d_g[(size_t)2 * M_ * G4_];               // [dir][t(or s)][b][1024]
__device__ float d_h[(size_t)M_ * 2 * H_];                // [b][t][512] = [h_f | h_b]
__device__ float d_emis[(size_t)M_ * L_];                 // [b][t][15]
__device__ float d_hbuf[2 * 8 * 2 * 2048];                // [dir][bbt][buf][unit*8+batch]
__device__ float d_partial[B_];
__device__ unsigned g_cnt[16];                            // per (dir,bbt) group counters

// ------------------------- helpers -------------------------
__device__ __forceinline__ float sigm(float x) {
    float e = __expf(-x);
    return __fdividef(1.0f, 1.0f + e);
}
__device__ __forceinline__ float tanh_ap(float x) {
    float y;
    asm("tanh.approx.f32 %0, %1;" : "=f"(y) : "f"(x));
    return y;
}
__device__ __forceinline__ float sel4(float4 v, int j) {
    float x = v.x;
    x = (j == 1) ? v.y : x;
    x = (j == 2) ? v.z : x;
    x = (j == 3) ? v.w : x;
    return x;
}
__device__ __forceinline__ uint32_t smem_u32(const void* p) {
    uint32_t a;
    asm("{ .reg .u64 t; cvta.to.shared.u64 t, %1; cvt.u32.u64 %0, t; }" : "=r"(a) : "l"(p));
    return a;
}
// packed f32x2 helpers
__device__ __forceinline__ unsigned long long pack2(float a, float b) {
    unsigned long long r;
    asm("mov.b64 %0, {%1, %2};" : "=l"(r) : "f"(a), "f"(b));
    return r;
}
__device__ __forceinline__ void ffma2(unsigned long long& d, unsigned long long a,
                                      unsigned long long b) {
    asm("fma.rn.f32x2 %0, %1, %2, %0;" : "+l"(d) : "l"(a), "l"(b));
}
__device__ __forceinline__ float2 unpack2(unsigned long long v) {
    float2 r;
    asm("mov.b64 {%0, %1}, %2;" : "=f"(r.x), "=f"(r.y) : "l"(v));
    return r;
}
// cp.async helpers (sm_80 base ISA)
__device__ __forceinline__ void cp_async16(uint32_t dst, const void* src) {
    asm volatile("cp.async.cg.shared.global [%0], [%1], 16;" :: "r"(dst), "l"(src));
}
#define CP_COMMIT() asm volatile("cp.async.commit_group;" ::: "memory")
#define CP_WAIT(n)  asm volatile("cp.async.wait_group %0;" :: "n"(n) : "memory")

// ------------------------- K0: reset barrier counters -------------------------
__global__ void k_init() {
    if (threadIdx.x < 16) g_cnt[threadIdx.x] = 0u;
}

// ------------------------- K1: embedding gather + concat + bf16 + pad -------------------------
__global__ void k_embed(const int* __restrict__ ids, const int* __restrict__ sids,
                        const float* __restrict__ emb, const float* __restrict__ semb) {
    int m = blockIdx.x;
    int c = threadIdx.x;
    __nv_bfloat16* xp = d_xb + (size_t)m * KP;
    if (c < 300) {
        int id = ids[m];
        int sid = sids[m];
        xp[c]       = __float2bfloat16_rn(emb[(size_t)id * 300 + c]);
        xp[300 + c] = __float2bfloat16_rn(semb[(size_t)sid * 300 + c]);
    } else {
        int z = c - 300;
        xp[600 + z] = __float2bfloat16_rn(0.f);
        xp[620 + z] = __float2bfloat16_rn(0.f);
    }
}

// ------------------------- K1b: weight conversion to bf16 (padded) -------------------------
__global__ void k_wconv(const float* __restrict__ Wf, const float* __restrict__ Wb) {
    int idx = blockIdx.x * blockDim.x + threadIdx.x;
    if (idx >= 2048 * KP) return;
    int row = idx / KP, k = idx - row * KP;
    float v = 0.f;
    if (k < KRAW) v = (row < 1024) ? Wf[row * KRAW + k] : Wb[(row - 1024) * KRAW + k];
    d_wb[idx] = __float2bfloat16_rn(v);
}

// ------------------------- K2: mma.sync bf16 GEMM, cp.async 3-stage pipeline -------------------------
#define APITCH 40
#define STAGE_ELEMS (128 * APITCH)          // bf16 elems per tile per stage
#define GSMEM_BYTES (3 * 2 * STAGE_ELEMS * 2)   // 3 stages x (A+B) x bf16 = 61440

__device__ __forceinline__ void ldm_x4(uint32_t* r, uint32_t addr) {
    asm volatile("ldmatrix.sync.aligned.m8n8.x4.shared.b16 {%0,%1,%2,%3}, [%4];"
                 : "=r"(r[0]), "=r"(r[1]), "=r"(r[2]), "=r"(r[3]) : "r"(addr));
}
__device__ __forceinline__ void mma16816(float* c, const uint32_t* a, const uint32_t* b) {
    asm volatile(
        "mma.sync.aligned.m16n8k16.row.col.f32.bf16.bf16.f32 "
        "{%0,%1,%2,%3}, {%4,%5,%6,%7}, {%8,%9}, {%0,%1,%2,%3};"
        : "+f"(c[0]), "+f"(c[1]), "+f"(c[2]), "+f"(c[3])
        : "r"(a[0]), "r"(a[1]), "r"(a[2]), "r"(a[3]), "r"(b[0]), "r"(b[1]));
}

__global__ void __launch_bounds__(256, 2)
k_gemm_mma(const float* __restrict__ bihf, const float* __restrict__ bhhf,
           const float* __restrict__ bihb, const float* __restrict__ bhhb,
           const int* __restrict__ lengths) {
    extern __shared__ __align__(16) __nv_bfloat16 smem[];
    __nv_bfloat16* sA = smem;                      // [3][128][APITCH]
    __nv_bfloat16* sB = smem + 3 * STAGE_ELEMS;    // [3][128][APITCH]

    int tid = threadIdx.x;
    int wid = tid >> 5;
    int lane = tid & 31;
    int warpM = wid & 3;
    int warpN = wid >> 2;
    int m0 = blockIdx.y * 128;
    int n0g = blockIdx.x * 128;
    int dir = n0g >> 10;
    int n0 = n0g & 1023;

    const __nv_bfloat16* xa = d_xb + (size_t)m0 * KP;
    const __nv_bfloat16* wa = d_wb + (size_t)n0g * KP;

    int v0 = tid * 2;
    int r0i = v0 >> 2, j0 = v0 & 3;
    int v1 = v0 + 1;
    int r1i = v1 >> 2, j1 = v1 & 3;

    uint32_t sA0 = smem_u32(&sA[r0i * APITCH + j0 * 8]);
    uint32_t sA1 = smem_u32(&sA[r1i * APITCH + j1 * 8]);
    uint32_t sB0 = smem_u32(&sB[r0i * APITCH + j0 * 8]);
    uint32_t sB1 = smem_u32(&sB[r1i * APITCH + j1 * 8]);
    const uint32_t stageB = STAGE_ELEMS * 2;   // bytes per stage

    float acc[2][8][4];
#pragma unroll
    for (int mf = 0; mf < 2; mf++)
#pragma unroll
        for (int nf = 0; nf < 8; nf++)
#pragma unroll
            for (int q = 0; q < 4; q++) acc[mf][nf][q] = 0.f;

    // prologue: issue chunks 0 and 1
#pragma unroll
    for (int s = 0; s < 2; s++) {
        const __nv_bfloat16* xan = xa + s * 32;
        const __nv_bfloat16* wan = wa + s * 32;
        cp_async16(sA0 + s * stageB, xan + (size_t)r0i * KP + j0 * 8);
        cp_async16(sA1 + s * stageB, xan + (size_t)r1i * KP + j1 * 8);
        cp_async16(sB0 + s * stageB, wan + (size_t)r0i * KP + j0 * 8);
        cp_async16(sB1 + s * stageB, wan + (size_t)r1i * KP + j1 * 8);
        CP_COMMIT();
    }
    CP_WAIT(1);
    __syncthreads();

    int aRow = warpM * 32 + (lane & 15);
    int aCol = (lane >> 4) << 3;
    int bRowBase = warpN * 64 + ((lane >> 4) << 3) + (lane & 7);
    int bCol = ((lane >> 3) & 1) << 3;

    for (int c = 0; c < 20; c++) {
        int buf = c % 3;
        if (c + 2 < 20) {
            int nb = (c + 2) % 3;
            const __nv_bfloat16* xan = xa + (c + 2) * 32;
            const __nv_bfloat16* wan = wa + (c + 2) * 32;
            cp_async16(sA0 + nb * stageB, xan + (size_t)r0i * KP + j0 * 8);
            cp_async16(sA1 + nb * stageB, xan + (size_t)r1i * KP + j1 * 8);
            cp_async16(sB0 + nb * stageB, wan + (size_t)r0i * KP + j0 * 8);
            cp_async16(sB1 + nb * stageB, wan + (size_t)r1i * KP + j1 * 8);
            CP_COMMIT();
        }
        const __nv_bfloat16* bufA = sA + buf * STAGE_ELEMS;
        const __nv_bfloat16* bufB = sB + buf * STAGE_ELEMS;
#pragma unroll
        for (int ks = 0; ks < 2; ks++) {
            int kc = ks * 16;
            uint32_t af[2][4];
#pragma unroll
            for (int mf = 0; mf < 2; mf++)
                ldm_x4(af[mf], smem_u32(&bufA[(aRow + mf * 16) * APITCH + kc + aCol]));
            uint32_t bf[4][4];
#pragma unroll
            for (int p = 0; p < 4; p++)
                ldm_x4(bf[p], smem_u32(&bufB[(bRowBase + p * 16) * APITCH + kc + bCol]));
#pragma unroll
            for (int mf = 0; mf < 2; mf++)
#pragma unroll
                for (int nf = 0; nf < 8; nf++)
                    mma16816(acc[mf][nf], af[mf], &bf[nf >> 1][(nf & 1) * 2]);
        }
        if (c + 1 < 20) {
            if (c + 2 < 20) { CP_WAIT(1); } else { CP_WAIT(0); }
            __syncthreads();
        }
    }

    const float* bihp = dir ? bihb : bihf;
    const float* bhhp = dir ? bhhb : bhhf;
    int groupID = lane >> 2;
    int qn = (lane & 3) * 2;
#pragma unroll
    for (int mf = 0; mf < 2; mf++) {
#pragma unroll
        for (int mr = 0; mr < 2; mr++) {
            int m = m0 + warpM * 32 + mf * 16 + groupID + mr * 8;
            int b = m >> 8, t = m & 255;
            int row = t;
            if (dir) {
                int len = lengths[b];
                row = (t < len) ? (len - 1 - t) : t;
            }
            float* outp = d_g + ((size_t)dir * M_ + (size_t)row * B_ + b) * G4_;
#pragma unroll
            for (int nf = 0; nf < 8; nf++) {
                int n = n0 + warpN * 64 + nf * 8 + qn;
                float2 o;
                o.x = acc[mf][nf][mr * 2 + 0] + bihp[n] + bhhp[n];
                o.y = acc[mf][nf][mr * 2 + 1] + bihp[n + 1] + bhhp[n + 1];
                *(float2*)(outp + n) = o;
            }
        }
    }
}

// ------------------------- K3: persistent bidirectional LSTM recurrence -------------------------
// R9 structure; barrier switched to release-atomic + acquire-poll (no MEMBAR.GPU).
__global__ void __launch_bounds__(256, 1)
k_rec(const float* __restrict__ Whh_f, const float* __restrict__ Whh_b,
      const int* __restrict__ lengths) {
    __shared__ __align__(16) float sH[2048];   // [unit*8 + batch]
    __shared__ float4 sRed[8 * 8 * 32];        // [kc][bb][rowgroup] partial gate sums

    int tid = threadIdx.x;
    int bx = blockIdx.x;
    int dir = bx >> 6;
    int r6 = bx & 63;
    int bbt = r6 >> 3;
    int ut = r6 & 7;
    int u0 = ut * 32;
    int grp = dir * 8 + bbt;
    const float* Whh = dir ? Whh_b : Whh_f;
    const float* gbase = d_g + (size_t)dir * M_ * G4_;
    float* hbufGrp = d_hbuf + (size_t)grp * 2 * 2048;

    int kc = tid >> 5;   // 0..7 (uniform per warp)
    int rg = tid & 31;   // 0..31

    int bb2 = tid >> 5;  // 0..7
    int q2 = tid & 31;   // 0..31
    int batch2 = bbt * 8 + bb2;
    int len2 = lengths[batch2];
    int jsel = q2 & 3;

    // Whh slice in registers
    float W[4][32];
#pragma unroll
    for (int j = 0; j < 4; j++) {
        int r = rg * 4 + j;
        int grow = (r >> 5) * 256 + u0 + (r & 31);
        const float* wp = Whh + (size_t)grow * 256 + kc * 32;
#pragma unroll
        for (int kk = 0; kk < 32; kk += 4) {
            float4 v = *(const float4*)(wp + kk);
            W[j][kk] = v.x; W[j][kk + 1] = v.y; W[j][kk + 2] = v.z; W[j][kk + 3] = v.w;
        }
    }

    for (int i = tid; i < 2048; i += 256) sH[i] = 0.f;

    float c = 0.f;
    unsigned target = 0;
    __syncthreads();

    // preload step 0's gates
    float gpre[4];
    {
        const float* gx = gbase + (size_t)batch2 * G4_;
#pragma unroll
        for (int g = 0; g < 4; g++) gpre[g] = gx[g * 256 + u0 + q2];
    }

    for (int step = 0; step < 256; step++) {
        // issue NEXT step's gate loads now (full-step latency cover)
        float gnxt[4];
        if (step + 1 < 256) {
            const float* gx = gbase + ((size_t)(step + 1) * B_ + batch2) * G4_;
#pragma unroll
            for (int g = 0; g < 4; g++) gnxt[g] = __ldcg(&gx[g * 256 + u0 + q2]);
        }

        // ---- phase 1: packed f32x2 partials, h octets via LDS.128 ----
        unsigned long long acc2[4][4];
#pragma unroll
        for (int p = 0; p < 4; p++)
#pragma unroll
            for (int j = 0; j < 4; j++) acc2[p][j] = pack2(0.f, 0.f);

        const ulonglong2* hp2 = (const ulonglong2*)&sH[kc * 256];
#pragma unroll
        for (int kk = 0; kk < 32; kk++) {
            ulonglong2 ha = hp2[kk * 2 + 0];
            ulonglong2 hb = hp2[kk * 2 + 1];
            unsigned long long h0 = ha.x, h1 = ha.y, h2 = hb.x, h3 = hb.y;
#pragma unroll
            for (int j = 0; j < 4; j++) {
                unsigned long long w2 = pack2(W[j][kk], W[j][kk]);
                ffma2(acc2[0][j], h0, w2);
                ffma2(acc2[1][j], h1, w2);
                ffma2(acc2[2][j], h2, w2);
                ffma2(acc2[3][j], h3, w2);
            }
        }
#pragma unroll
        for (int p = 0; p < 4; p++) {
            float4 lo, hi;
            float2 u0v = unpack2(acc2[p][0]);
            float2 u1v = unpack2(acc2[p][1]);
            float2 u2v = unpack2(acc2[p][2]);
            float2 u3v = unpack2(acc2[p][3]);
            lo.x = u0v.x; lo.y = u1v.x; lo.z = u2v.x; lo.w = u3v.x;
            hi.x = u0v.y; hi.y = u1v.y; hi.z = u2v.y; hi.w = u3v.y;
            sRed[(kc * 8 + p * 2 + 0) * 32 + rg] = lo;
            sRed[(kc * 8 + p * 2 + 1) * 32 + rg] = hi;
        }
        __syncthreads();

        // ---- phase 2: gates, cell update, h out ----
        float gate[4];
#pragma unroll
        for (int g = 0; g < 4; g++) {
            int rgl = g * 8 + (q2 >> 2);
            float s = gpre[g];
#pragma unroll
            for (int kcc = 0; kcc < 8; kcc++)
                s += sel4(sRed[(kcc * 8 + bb2) * 32 + rgl], jsel);
            gate[g] = s;
        }
        float i_ = sigm(gate[0]);
        float f_ = sigm(gate[1]);
        float gg = tanh_ap(gate[2]);
        float o_ = sigm(gate[3]);
        c = f_ * c + i_ * gg;
        float h = o_ * tanh_ap(c);

        int wbuf = step & 1;
        __stcg(&hbufGrp[wbuf * 2048 + (u0 + q2) * 8 + bb2], h);
        int tout = dir ? ((step < len2) ? (len2 - 1 - step) : step) : step;
        d_h[((size_t)batch2 * T_ + tout) * 512 + dir * 256 + u0 + q2] = h;

        // ---- group barrier: release-atomic + acquire-poll ----
        __syncthreads();           // orders all threads' stores before tid0's release
        target += 8;
        if (tid == 0) {
            asm volatile("red.release.gpu.global.add.u32 [%0], %1;"
                         :: "l"(&g_cnt[grp]), "r"(1u) : "memory");
            unsigned v;
            do {
                asm volatile("ld.acquire.gpu.global.u32 %0, [%1];"
                             : "=r"(v) : "l"(&g_cnt[grp]) : "memory");
            } while (v < target);
        }
        __syncthreads();

        // ---- reload full h_prev ----
        const float4* src = (const float4*)(hbufGrp + wbuf * 2048);
        ((float4*)sH)[tid]       = __ldcg(src + tid);
        ((float4*)sH)[tid + 256] = __ldcg(src + tid + 256);
        __syncthreads();

#pragma unroll
        for (int g = 0; g < 4; g++) gpre[g] = gnxt[g];
    }
}

// ------------------------- K4: emissions = h . Wlin^T + blin -------------------------
__global__ void __launch_bounds__(128)
k_emis(const float* __restrict__ Wlin, const float* __restrict__ blin) {
    __shared__ float sW[15 * 516];
    __shared__ float sh[8 * 512];
    int tid = threadIdx.x;
    for (int i = tid; i < 15 * 512; i += 128) {
        int l = i >> 9, k = i & 511;
        sW[l * 516 + k] = Wlin[i];
    }
    int m0 = blockIdx.x * 8;
    const float4* hsrc = (const float4*)(d_h + (size_t)m0 * 512);
    for (int i = tid; i < 8 * 512 / 4; i += 128)
        ((float4*)sh)[i] = hsrc[i];
    __syncthreads();

    int r = tid >> 4, l = tid & 15;
    if (l < 15) {
        float s = blin[l];
        const float* hw = sh + r * 512;
        const float* ww = sW + l * 516;
#pragma unroll 8
        for (int k = 0; k < 512; k += 4) {
            float4 hv = *(const float4*)(hw + k);
            float4 wv = *(const float4*)(ww + k);
            s += hv.x * wv.x + hv.y * wv.y + hv.z * wv.z + hv.w * wv.w;
        }
        d_emis[(size_t)(m0 + r) * L_ + l] = s;
    }
}

// ------------------------- K5: CRF NLL per sequence -------------------------
__global__ void k_crf(const int* __restrict__ lengths, const int* __restrict__ labels,
                      const float* __restrict__ start_t, const float* __restrict__ end_t,
                      const float* __restrict__ trans) {
    int b = blockIdx.x;
    int lane = threadIdx.x;
    int len = lengths[b];
    const float* em = d_emis + (size_t)b * T_ * L_;
    int j = (lane < L_) ? lane : 0;

    float tr[L_];
#pragma unroll
    for (int i = 0; i < L_; i++) tr[i] = trans[i * L_ + j];

    float alpha = start_t[j] + em[j];
    for (int t = 1; t < T_; t++) {
        float v[L_], mx = -1e30f;
#pragma unroll
        for (int i = 0; i < L_; i++) {
            float av = __shfl_sync(0xffffffffu, alpha, i);
            v[i] = av + tr[i];
            mx = fmaxf(mx, v[i]);
        }
        float s = 0.f;
#pragma unroll
        for (int i = 0; i < L_; i++) s += __expf(v[i] - mx);
        float nxt = mx + __logf(s) + em[t * L_ + j];
        if (t < len) alpha = nxt;
    }
    float vv = (lane < L_) ? (alpha + end_t[lane]) : -1e30f;
    float mx = vv;
#pragma unroll
    for (int o = 16; o; o >>= 1) mx = fmaxf(mx, __shfl_xor_sync(0xffffffffu, mx, o));
    float se = (lane < L_) ? __expf(vv - mx) : 0.f;
#pragma unroll
    for (int o = 16; o; o >>= 1) se += __shfl_xor_sync(0xffffffffu, se, o);
    float den = mx + __logf(se);

    const int* tg = labels + b * T_;
    float em_s = 0.f, tr_s = 0.f;
    for (int t = lane; t < T_; t += 32) {
        if (t < len) {
            em_s += em[t * L_ + tg[t]];
            if (t >= 1) tr_s += trans[tg[t - 1] * L_ + tg[t]];
        }
    }
#pragma unroll
    for (int o = 16; o; o >>= 1) {
        em_s += __shfl_xor_sync(0xffffffffu, em_s, o);
        tr_s += __shfl_xor_sync(0xffffffffu, tr_s, o);
    }
    if (lane == 0) {
        float num = start_t[tg[0]] + em_s + tr_s + end_t[tg[len - 1]];
        d_partial[b] = num - den;
    }
}

// ------------------------- K6: deterministic final sum -------------------------
__global__ void k_final(float* __restrict__ out) {
    float s = 0.f;
#pragma unroll
    for (int b = 0; b < B_; b++) s += d_partial[b];
    out[0] = -s;
}

// ------------------------- launch -------------------------
extern "C" void kernel_launch(void* const* d_in, const int* in_sizes, int n_in,
                              void* d_out, int out_size) {
    const int*   input_ids    = (const int*)d_in[0];
    const int*   lengths      = (const int*)d_in[1];
    const int*   softword_ids = (const int*)d_in[2];
    const int*   label_ids    = (const int*)d_in[3];
    const float* emb          = (const float*)d_in[4];
    const float* soft_emb     = (const float*)d_in[5];
    const float* Wih_f        = (const float*)d_in[6];
    const float* Whh_f        = (const float*)d_in[7];
    const float* bih_f        = (const float*)d_in[8];
    const float* bhh_f        = (const float*)d_in[9];
    const float* Wih_b        = (const float*)d_in[10];
    const float* Whh_b        = (const float*)d_in[11];
    const float* bih_b        = (const float*)d_in[12];
    const float* bhh_b        = (const float*)d_in[13];
    const float* Wlin         = (const float*)d_in[14];
    const float* blin         = (const float*)d_in[15];
    const float* start_t      = (const float*)d_in[16];
    const float* end_t        = (const float*)d_in[17];
    const float* trans        = (const float*)d_in[18];
    float* out = (float*)d_out;

    cudaFuncSetAttribute(k_gemm_mma, cudaFuncAttributeMaxDynamicSharedMemorySize, GSMEM_BYTES);

    k_init<<<1, 32>>>();
    k_embed<<<M_, 320>>>(input_ids, softword_ids, emb, soft_emb);
    k_wconv<<<(2048 * KP + 511) / 512, 512>>>(Wih_f, Wih_b);
    dim3 g2(16, 128);
    k_gemm_mma<<<g2, 256, GSMEM_BYTES>>>(bih_f, bhh_f, bih_b, bhh_b, lengths);
    k_rec<<<128, 256>>>(Whh_f, Whh_b, lengths);
    k_emis<<<2048, 128>>>(Wlin, blin);
    k_crf<<<B_, 32>>>(lengths, label_ids, start_t, end_t, trans);
    k_final<<<1, 1>>>(out);
}

// round 11
// speedup vs baseline: 1.8538x; 1.0200x over previous
#include <cuda_runtime.h>
#include <cuda_bf16.h>
#include <cstdint>

// Problem constants
#define B_ 64
#define T_ 256
#define H_ 256
#define G4_ 1024      // 4*H
#define KRAW 600      // 2*E
#define KP 640        // padded K (20 chunks of 32)
#define L_ 15
#define M_ (B_*T_)    // 16384

// ------------------------- device scratch (no allocations) -------------------------
__device__ __align__(16) __nv_bfloat16 d_xb[(size_t)M_ * KP];    // [16384, 640] bf16
__device__ __align__(16) __nv_bfloat16 d_wb[(size_t)2048 * KP];  // [2048, 640] bf16
__device__ float d_g[(size_t)2 * M_ * G4_];               // [dir][t(or s)][b][1024]
__device__ float d_h[(size_t)M_ * 2 * H_];                // [b][t][512] = [h_f | h_b]
__device__ float d_emis[(size_t)M_ * L_];                 // [b][t][15]
__device__ float d_hbuf[2 * 8 * 2 * 2048];                // [dir][bbt][buf][unit*8+batch]
__device__ float d_partial[B_];
__device__ unsigned g_flag[128];                          // per-block step counters

// ------------------------- helpers -------------------------
__device__ __forceinline__ float sigm(float x) {
    float e = __expf(-x);
    return __fdividef(1.0f, 1.0f + e);
}
__device__ __forceinline__ float tanh_ap(float x) {
    float y;
    asm("tanh.approx.f32 %0, %1;" : "=f"(y) : "f"(x));
    return y;
}
__device__ __forceinline__ float sel4(float4 v, int j) {
    float x = v.x;
    x = (j == 1) ? v.y : x;
    x = (j == 2) ? v.z : x;
    x = (j == 3) ? v.w : x;
    return x;
}
__device__ __forceinline__ uint32_t smem_u32(const void* p) {
    uint32_t a;
    asm("{ .reg .u64 t; cvta.to.shared.u64 t, %1; cvt.u32.u64 %0, t; }" : "=r"(a) : "l"(p));
    return a;
}
// packed f32x2 helpers
__device__ __forceinline__ unsigned long long pack2(float a, float b) {
    unsigned long long r;
    asm("mov.b64 %0, {%1, %2};" : "=l"(r) : "f"(a), "f"(b));
    return r;
}
__device__ __forceinline__ void ffma2(unsigned long long& d, unsigned long long a,
                                      unsigned long long b) {
    asm("fma.rn.f32x2 %0, %1, %2, %0;" : "+l"(d) : "l"(a), "l"(b));
}
__device__ __forceinline__ float2 unpack2(unsigned long long v) {
    float2 r;
    asm("mov.b64 {%0, %1}, %2;" : "=f"(r.x), "=f"(r.y) : "l"(v));
    return r;
}
// cp.async helpers (sm_80 base ISA)
__device__ __forceinline__ void cp_async16(uint32_t dst, const void* src) {
    asm volatile("cp.async.cg.shared.global [%0], [%1], 16;" :: "r"(dst), "l"(src));
}
#define CP_COMMIT() asm volatile("cp.async.commit_group;" ::: "memory")
#define CP_WAIT(n)  asm volatile("cp.async.wait_group %0;" :: "n"(n) : "memory")

// ------------------------- K0: reset flags -------------------------
__global__ void k_init() {
    if (threadIdx.x < 128) g_flag[threadIdx.x] = 0u;
}

// ------------------------- K1: embedding gather + concat + bf16 + pad -------------------------
__global__ void k_embed(const int* __restrict__ ids, const int* __restrict__ sids,
                        const float* __restrict__ emb, const float* __restrict__ semb) {
    int m = blockIdx.x;
    int c = threadIdx.x;
    __nv_bfloat16* xp = d_xb + (size_t)m * KP;
    if (c < 300) {
        int id = ids[m];
        int sid = sids[m];
        xp[c]       = __float2bfloat16_rn(emb[(size_t)id * 300 + c]);
        xp[300 + c] = __float2bfloat16_rn(semb[(size_t)sid * 300 + c]);
    } else {
        int z = c - 300;
        xp[600 + z] = __float2bfloat16_rn(0.f);
        xp[620 + z] = __float2bfloat16_rn(0.f);
    }
}

// ------------------------- K1b: weight conversion to bf16 (padded) -------------------------
__global__ void k_wconv(const float* __restrict__ Wf, const float* __restrict__ Wb) {
    int idx = blockIdx.x * blockDim.x + threadIdx.x;
    if (idx >= 2048 * KP) return;
    int row = idx / KP, k = idx - row * KP;
    float v = 0.f;
    if (k < KRAW) v = (row < 1024) ? Wf[row * KRAW + k] : Wb[(row - 1024) * KRAW + k];
    d_wb[idx] = __float2bfloat16_rn(v);
}

// ------------------------- K2: mma.sync bf16 GEMM, cp.async 3-stage (R10, proven) -------------------------
#define APITCH 40
#define STAGE_ELEMS (128 * APITCH)
#define GSMEM_BYTES (3 * 2 * STAGE_ELEMS * 2)

__device__ __forceinline__ void ldm_x4(uint32_t* r, uint32_t addr) {
    asm volatile("ldmatrix.sync.aligned.m8n8.x4.shared.b16 {%0,%1,%2,%3}, [%4];"
                 : "=r"(r[0]), "=r"(r[1]), "=r"(r[2]), "=r"(r[3]) : "r"(addr));
}
__device__ __forceinline__ void mma16816(float* c, const uint32_t* a, const uint32_t* b) {
    asm volatile(
        "mma.sync.aligned.m16n8k16.row.col.f32.bf16.bf16.f32 "
        "{%0,%1,%2,%3}, {%4,%5,%6,%7}, {%8,%9}, {%0,%1,%2,%3};"
        : "+f"(c[0]), "+f"(c[1]), "+f"(c[2]), "+f"(c[3])
        : "r"(a[0]), "r"(a[1]), "r"(a[2]), "r"(a[3]), "r"(b[0]), "r"(b[1]));
}

__global__ void __launch_bounds__(256, 2)
k_gemm_mma(const float* __restrict__ bihf, const float* __restrict__ bhhf,
           const float* __restrict__ bihb, const float* __restrict__ bhhb,
           const int* __restrict__ lengths) {
    extern __shared__ __align__(16) __nv_bfloat16 smem[];
    __nv_bfloat16* sA = smem;
    __nv_bfloat16* sB = smem + 3 * STAGE_ELEMS;

    int tid = threadIdx.x;
    int wid = tid >> 5;
    int lane = tid & 31;
    int warpM = wid & 3;
    int warpN = wid >> 2;
    int m0 = blockIdx.y * 128;
    int n0g = blockIdx.x * 128;
    int dir = n0g >> 10;
    int n0 = n0g & 1023;

    const __nv_bfloat16* xa = d_xb + (size_t)m0 * KP;
    const __nv_bfloat16* wa = d_wb + (size_t)n0g * KP;

    int v0 = tid * 2;
    int r0i = v0 >> 2, j0 = v0 & 3;
    int v1 = v0 + 1;
    int r1i = v1 >> 2, j1 = v1 & 3;

    uint32_t sA0 = smem_u32(&sA[r0i * APITCH + j0 * 8]);
    uint32_t sA1 = smem_u32(&sA[r1i * APITCH + j1 * 8]);
    uint32_t sB0 = smem_u32(&sB[r0i * APITCH + j0 * 8]);
    uint32_t sB1 = smem_u32(&sB[r1i * APITCH + j1 * 8]);
    const uint32_t stageB = STAGE_ELEMS * 2;

    float acc[2][8][4];
#pragma unroll
    for (int mf = 0; mf < 2; mf++)
#pragma unroll
        for (int nf = 0; nf < 8; nf++)
#pragma unroll
            for (int q = 0; q < 4; q++) acc[mf][nf][q] = 0.f;

#pragma unroll
    for (int s = 0; s < 2; s++) {
        const __nv_bfloat16* xan = xa + s * 32;
        const __nv_bfloat16* wan = wa + s * 32;
        cp_async16(sA0 + s * stageB, xan + (size_t)r0i * KP + j0 * 8);
        cp_async16(sA1 + s * stageB, xan + (size_t)r1i * KP + j1 * 8);
        cp_async16(sB0 + s * stageB, wan + (size_t)r0i * KP + j0 * 8);
        cp_async16(sB1 + s * stageB, wan + (size_t)r1i * KP + j1 * 8);
        CP_COMMIT();
    }
    CP_WAIT(1);
    __syncthreads();

    int aRow = warpM * 32 + (lane & 15);
    int aCol = (lane >> 4) << 3;
    int bRowBase = warpN * 64 + ((lane >> 4) << 3) + (lane & 7);
    int bCol = ((lane >> 3) & 1) << 3;

    for (int c = 0; c < 20; c++) {
        int buf = c % 3;
        if (c + 2 < 20) {
            int nb = (c + 2) % 3;
            const __nv_bfloat16* xan = xa + (c + 2) * 32;
            const __nv_bfloat16* wan = wa + (c + 2) * 32;
            cp_async16(sA0 + nb * stageB, xan + (size_t)r0i * KP + j0 * 8);
            cp_async16(sA1 + nb * stageB, xan + (size_t)r1i * KP + j1 * 8);
            cp_async16(sB0 + nb * stageB, wan + (size_t)r0i * KP + j0 * 8);
            cp_async16(sB1 + nb * stageB, wan + (size_t)r1i * KP + j1 * 8);
            CP_COMMIT();
        }
        const __nv_bfloat16* bufA = sA + buf * STAGE_ELEMS;
        const __nv_bfloat16* bufB = sB + buf * STAGE_ELEMS;
#pragma unroll
        for (int ks = 0; ks < 2; ks++) {
            int kc = ks * 16;
            uint32_t af[2][4];
#pragma unroll
            for (int mf = 0; mf < 2; mf++)
                ldm_x4(af[mf], smem_u32(&bufA[(aRow + mf * 16) * APITCH + kc + aCol]));
            uint32_t bf[4][4];
#pragma unroll
            for (int p = 0; p < 4; p++)
                ldm_x4(bf[p], smem_u32(&bufB[(bRowBase + p * 16) * APITCH + kc + bCol]));
#pragma unroll
            for (int mf = 0; mf < 2; mf++)
#pragma unroll
                for (int nf = 0; nf < 8; nf++)
                    mma16816(acc[mf][nf], af[mf], &bf[nf >> 1][(nf & 1) * 2]);
        }
        if (c + 1 < 20) {
            if (c + 2 < 20) { CP_WAIT(1); } else { CP_WAIT(0); }
            __syncthreads();
        }
    }

    const float* bihp = dir ? bihb : bihf;
    const float* bhhp = dir ? bhhb : bhhf;
    int groupID = lane >> 2;
    int qn = (lane & 3) * 2;
#pragma unroll
    for (int mf = 0; mf < 2; mf++) {
#pragma unroll
        for (int mr = 0; mr < 2; mr++) {
            int m = m0 + warpM * 32 + mf * 16 + groupID + mr * 8;
            int b = m >> 8, t = m & 255;
            int row = t;
            if (dir) {
                int len = lengths[b];
                row = (t < len) ? (len - 1 - t) : t;
            }
            float* outp = d_g + ((size_t)dir * M_ + (size_t)row * B_ + b) * G4_;
#pragma unroll
            for (int nf = 0; nf < 8; nf++) {
                int n = n0 + warpN * 64 + nf * 8 + qn;
                float2 o;
                o.x = acc[mf][nf][mr * 2 + 0] + bihp[n] + bhhp[n];
                o.y = acc[mf][nf][mr * 2 + 1] + bihp[n + 1] + bhhp[n + 1];
                *(float2*)(outp + n) = o;
            }
        }
    }
}

// ------------------------- K3: persistent bidirectional LSTM recurrence -------------------------
// R10 core; monolithic group barrier replaced by per-producer dataflow flags:
// warp kc waits only on block (dir,bbt,kc)'s flag and loads only that 256-float chunk.
__global__ void __launch_bounds__(256, 1)
k_rec(const float* __restrict__ Whh_f, const float* __restrict__ Whh_b,
      const int* __restrict__ lengths) {
    __shared__ __align__(16) float sH[2048];   // [unit*8 + batch]; warp-private 256-float chunks
    __shared__ float4 sRed[8 * 8 * 32];        // [kc][bb][rowgroup] partial gate sums

    int tid = threadIdx.x;
    int bx = blockIdx.x;
    int dir = bx >> 6;
    int r6 = bx & 63;
    int bbt = r6 >> 3;
    int ut = r6 & 7;
    int u0 = ut * 32;
    const float* Whh = dir ? Whh_b : Whh_f;
    const float* gbase = d_g + (size_t)dir * M_ * G4_;
    int grp = dir * 8 + bbt;
    float* hbufGrp = d_hbuf + (size_t)grp * 2 * 2048;
    unsigned fbase = (unsigned)(grp * 8);      // flags of this group's 8 blocks

    int kc = tid >> 5;   // 0..7 (uniform per warp)
    int rg = tid & 31;   // 0..31
    int lane = rg;

    int bb2 = tid >> 5;  // 0..7
    int q2 = tid & 31;   // 0..31
    int batch2 = bbt * 8 + bb2;
    int len2 = lengths[batch2];
    int jsel = q2 & 3;

    // Whh slice in registers
    float W[4][32];
#pragma unroll
    for (int j = 0; j < 4; j++) {
        int r = rg * 4 + j;
        int grow = (r >> 5) * 256 + u0 + (r & 31);
        const float* wp = Whh + (size_t)grow * 256 + kc * 32;
#pragma unroll
        for (int kk = 0; kk < 32; kk += 4) {
            float4 v = *(const float4*)(wp + kk);
            W[j][kk] = v.x; W[j][kk + 1] = v.y; W[j][kk + 2] = v.z; W[j][kk + 3] = v.w;
        }
    }

    for (int i = tid; i < 2048; i += 256) sH[i] = 0.f;

    float c = 0.f;
    __syncthreads();

    // preload step 0's gates
    float gpre[4];
    {
        const float* gx = gbase + (size_t)batch2 * G4_;
#pragma unroll
        for (int g = 0; g < 4; g++) gpre[g] = gx[g * 256 + u0 + q2];
    }

    for (int step = 0; step < 256; step++) {
        // issue NEXT step's gate loads (full-step latency cover)
        float gnxt[4];
        if (step + 1 < 256) {
            const float* gx = gbase + ((size_t)(step + 1) * B_ + batch2) * G4_;
#pragma unroll
            for (int g = 0; g < 4; g++) gnxt[g] = __ldcg(&gx[g * 256 + u0 + q2]);
        }

        // ---- fetch this warp's h chunk from its single producer (step>0) ----
        if (step > 0) {
            if (lane == 0) {
                unsigned v;
                do {
                    asm volatile("ld.acquire.gpu.global.u32 %0, [%1];"
                                 : "=r"(v) : "l"(&g_flag[fbase + kc]) : "memory");
                } while (v < (unsigned)step);
            }
            __syncwarp();
            int rb = (step - 1) & 1;
            const float4* src = (const float4*)(hbufGrp + rb * 2048 + kc * 256);
            float4 a = __ldcg(src + lane);
            float4 b = __ldcg(src + 32 + lane);
            *(float4*)&sH[kc * 256 + lane * 4]       = a;
            *(float4*)&sH[kc * 256 + 128 + lane * 4] = b;
            __syncwarp();
        }

        // ---- phase 1: packed f32x2 partials, h octets via LDS.128 ----
        unsigned long long acc2[4][4];
#pragma unroll
        for (int p = 0; p < 4; p++)
#pragma unroll
            for (int j = 0; j < 4; j++) acc2[p][j] = pack2(0.f, 0.f);

        const ulonglong2* hp2 = (const ulonglong2*)&sH[kc * 256];
#pragma unroll
        for (int kk = 0; kk < 32; kk++) {
            ulonglong2 ha = hp2[kk * 2 + 0];
            ulonglong2 hb = hp2[kk * 2 + 1];
            unsigned long long h0 = ha.x, h1 = ha.y, h2 = hb.x, h3 = hb.y;
#pragma unroll
            for (int j = 0; j < 4; j++) {
                unsigned long long w2 = pack2(W[j][kk], W[j][kk]);
                ffma2(acc2[0][j], h0, w2);
                ffma2(acc2[1][j], h1, w2);
                ffma2(acc2[2][j], h2, w2);
                ffma2(acc2[3][j], h3, w2);
            }
        }
#pragma unroll
        for (int p = 0; p < 4; p++) {
            float4 lo, hi;
            float2 u0v = unpack2(acc2[p][0]);
            float2 u1v = unpack2(acc2[p][1]);
            float2 u2v = unpack2(acc2[p][2]);
            float2 u3v = unpack2(acc2[p][3]);
            lo.x = u0v.x; lo.y = u1v.x; lo.z = u2v.x; lo.w = u3v.x;
            hi.x = u0v.y; hi.y = u1v.y; hi.z = u2v.y; hi.w = u3v.y;
            sRed[(kc * 8 + p * 2 + 0) * 32 + rg] = lo;
            sRed[(kc * 8 + p * 2 + 1) * 32 + rg] = hi;
        }
        __syncthreads();

        // ---- phase 2: gates, cell update ----
        float gate[4];
#pragma unroll
        for (int g = 0; g < 4; g++) {
            int rgl = g * 8 + (q2 >> 2);
            float s = gpre[g];
#pragma unroll
            for (int kcc = 0; kcc < 8; kcc++)
                s += sel4(sRed[(kcc * 8 + bb2) * 32 + rgl], jsel);
            gate[g] = s;
        }
        float i_ = sigm(gate[0]);
        float f_ = sigm(gate[1]);
        float gg = tanh_ap(gate[2]);
        float o_ = sigm(gate[3]);
        c = f_ * c + i_ * gg;
        float h = o_ * tanh_ap(c);

        int wbuf = step & 1;
        __stcg(&hbufGrp[wbuf * 2048 + (u0 + q2) * 8 + bb2], h);

        // ---- publish: all h stores done -> release flag ASAP ----
        __syncthreads();
        if (tid == 0) {
            asm volatile("red.release.gpu.global.add.u32 [%0], %1;"
                         :: "l"(&g_flag[fbase + ut]), "r"(1u) : "memory");
        }

        // d_h store off the critical path
        int tout = dir ? ((step < len2) ? (len2 - 1 - step) : step) : step;
        d_h[((size_t)batch2 * T_ + tout) * 512 + dir * 256 + u0 + q2] = h;

#pragma unroll
        for (int g = 0; g < 4; g++) gpre[g] = gnxt[g];
    }
}

// ------------------------- K4: emissions = h . Wlin^T + blin -------------------------
__global__ void __launch_bounds__(128)
k_emis(const float* __restrict__ Wlin, const float* __restrict__ blin) {
    __shared__ float sW[15 * 516];
    __shared__ float sh[8 * 512];
    int tid = threadIdx.x;
    for (int i = tid; i < 15 * 512; i += 128) {
        int l = i >> 9, k = i & 511;
        sW[l * 516 + k] = Wlin[i];
    }
    int m0 = blockIdx.x * 8;
    const float4* hsrc = (const float4*)(d_h + (size_t)m0 * 512);
    for (int i = tid; i < 8 * 512 / 4; i += 128)
        ((float4*)sh)[i] = hsrc[i];
    __syncthreads();

    int r = tid >> 4, l = tid & 15;
    if (l < 15) {
        float s = blin[l];
        const float* hw = sh + r * 512;
        const float* ww = sW + l * 516;
#pragma unroll 8
        for (int k = 0; k < 512; k += 4) {
            float4 hv = *(const float4*)(hw + k);
            float4 wv = *(const float4*)(ww + k);
            s += hv.x * wv.x + hv.y * wv.y + hv.z * wv.z + hv.w * wv.w;
        }
        d_emis[(size_t)(m0 + r) * L_ + l] = s;
    }
}

// ------------------------- K5: CRF NLL per sequence -------------------------
__global__ void k_crf(const int* __restrict__ lengths, const int* __restrict__ labels,
                      const float* __restrict__ start_t, const float* __restrict__ end_t,
                      const float* __restrict__ trans) {
    int b = blockIdx.x;
    int lane = threadIdx.x;
    int len = lengths[b];
    const float* em = d_emis + (size_t)b * T_ * L_;
    int j = (lane < L_) ? lane : 0;

    float tr[L_];
#pragma unroll
    for (int i = 0; i < L_; i++) tr[i] = trans[i * L_ + j];

    float alpha = start_t[j] + em[j];
    for (int t = 1; t < T_; t++) {
        float v[L_], mx = -1e30f;
#pragma unroll
        for (int i = 0; i < L_; i++) {
            float av = __shfl_sync(0xffffffffu, alpha, i);
            v[i] = av + tr[i];
            mx = fmaxf(mx, v[i]);
        }
        float s = 0.f;
#pragma unroll
        for (int i = 0; i < L_; i++) s += __expf(v[i] - mx);
        float nxt = mx + __logf(s) + em[t * L_ + j];
        if (t < len) alpha = nxt;
    }
    float vv = (lane < L_) ? (alpha + end_t[lane]) : -1e30f;
    float mx = vv;
#pragma unroll
    for (int o = 16; o; o >>= 1) mx = fmaxf(mx, __shfl_xor_sync(0xffffffffu, mx, o));
    float se = (lane < L_) ? __expf(vv - mx) : 0.f;
#pragma unroll
    for (int o = 16; o; o >>= 1) se += __shfl_xor_sync(0xffffffffu, se, o);
    float den = mx + __logf(se);

    const int* tg = labels + b * T_;
    float em_s = 0.f, tr_s = 0.f;
    for (int t = lane; t < T_; t += 32) {
        if (t < len) {
            em_s += em[t * L_ + tg[t]];
            if (t >= 1) tr_s += trans[tg[t - 1] * L_ + tg[t]];
        }
    }
#pragma unroll
    for (int o = 16; o; o >>= 1) {
        em_s += __shfl_xor_sync(0xffffffffu, em_s, o);
        tr_s += __shfl_xor_sync(0xffffffffu, tr_s, o);
    }
    if (lane == 0) {
        float num = start_t[tg[0]] + em_s + tr_s + end_t[tg[len - 1]];
        d_partial[b] = num - den;
    }
}

// ------------------------- K6: deterministic final sum -------------------------
__global__ void k_final(float* __restrict__ out) {
    float s = 0.f;
#pragma unroll
    for (int b = 0; b < B_; b++) s += d_partial[b];
    out[0] = -s;
}

// ------------------------- launch -------------------------
extern "C" void kernel_launch(void* const* d_in, const int* in_sizes, int n_in,
                              void* d_out, int out_size) {
    const int*   input_ids    = (const int*)d_in[0];
    const int*   lengths      = (const int*)d_in[1];
    const int*   softword_ids = (const int*)d_in[2];
    const int*   label_ids    = (const int*)d_in[3];
    const float* emb          = (const float*)d_in[4];
    const float* soft_emb     = (const float*)d_in[5];
    const float* Wih_f        = (const float*)d_in[6];
    const float* Whh_f        = (const float*)d_in[7];
    const float* bih_f        = (const float*)d_in[8];
    const float* bhh_f        = (const float*)d_in[9];
    const float* Wih_b        = (const float*)d_in[10];
    const float* Whh_b        = (const float*)d_in[11];
    const float* bih_b        = (const float*)d_in[12];
    const float* bhh_b        = (const float*)d_in[13];
    const float* Wlin         = (const float*)d_in[14];
    const float* blin         = (const float*)d_in[15];
    const float* start_t      = (const float*)d_in[16];
    const float* end_t        = (const float*)d_in[17];
    const float* trans        = (const float*)d_in[18];
    float* out = (float*)d_out;

    cudaFuncSetAttribute(k_gemm_mma, cudaFuncAttributeMaxDynamicSharedMemorySize, GSMEM_BYTES);

    k_init<<<1, 128>>>();
    k_embed<<<M_, 320>>>(input_ids, softword_ids, emb, soft_emb);
    k_wconv<<<(2048 * KP + 511) / 512, 512>>>(Wih_f, Wih_b);
    dim3 g2(16, 128);
    k_gemm_mma<<<g2, 256, GSMEM_BYTES>>>(bih_f, bhh_f, bih_b, bhh_b, lengths);
    k_rec<<<128, 256>>>(Whh_f, Whh_b, lengths);
    k_emis<<<2048, 128>>>(Wlin, blin);
    k_crf<<<B_, 32>>>(lengths, label_ids, start_t, end_t, trans);
    k_final<<<1, 1>>>(out);
}